// round 16
// baseline (speedup 1.0000x reference)
#include <cuda_runtime.h>
#include <math.h>
#include <stdint.h>

// Problem constants
#define NROWS   16384
#define HD      256
#define H3      768
#define TSTEPS  24

// Tiling
#define MTILE   128                  // rows per CTA
#define NBLK    (NROWS / MTILE)      // 128 CTAs
#define NTHREADS 512                 // 16 warps: 4 row-groups x 4 N-groups
#define UC      32                   // hidden units per chunk
#define NCH     (HD / UC)            // 8 chunks
#define NSEG    64                   // 8 chunks x 8 K-segments of 32
#define PITCH   260                  // h smem pitch (stride%32==4, conflict-free)
#define WP      40                   // W segment row pitch
#define WROWS   96                   // 3 gates x 32 units
#define WSEGW   (WROWS * WP)         // 3840 words per (hi|lo) segment
#define WBUFW   (2 * WSEGW)          // 7680 words per buffer (hi+lo)

// Persistent device state
__device__ float    g_h[NROWS * HD];        // hidden state [N,H]
__device__ float    g_A[H3];                // W_ih @ w_proj
__device__ float    g_C[H3];                // W_ih @ b_proj + b_ih
// W_hh pre-split tf32 hi/lo, chunk-major [8][96][256], cols pair-permuted
__device__ uint32_t g_Wp_hi[NCH * WROWS * HD];
__device__ uint32_t g_Wp_lo[NCH * WROWS * HD];

// smem words
#define SH_W    (MTILE * PITCH)              // 33280
#define SWB_W   SH_W                         // W buffers start
#define SA_W    (SWB_W + 2 * WBUFW)          // 48640
#define SX_W    (SA_W + 3 * H3 + HD)         // 51200
#define SPRED_W (SX_W + MTILE)               // 51328
#define SMEM_WORDS (SPRED_W + MTILE * 4)     // 51840
#define SMEM_BYTES (SMEM_WORDS * 4)          // 207360

// ---------------------------------------------------------------------------
__device__ __forceinline__ void split_tf32(float v, uint32_t& hi, uint32_t& lo)
{
    uint32_t h;
    asm("cvt.rna.tf32.f32 %0, %1;" : "=r"(h) : "f"(v));
    float lf = v - __uint_as_float(h);
    uint32_t l;
    asm("cvt.rna.tf32.f32 %0, %1;" : "=r"(l) : "f"(lf));
    hi = h; lo = l;
}

__device__ __forceinline__ uint32_t cvt_tf32(float v)
{
    uint32_t h;
    asm("cvt.rna.tf32.f32 %0, %1;" : "=r"(h) : "f"(v));
    return h;
}

__global__ void init_kernel(const float* __restrict__ enc,
                            const float* __restrict__ w_proj,
                            const float* __restrict__ b_proj,
                            const float* __restrict__ W_ih,
                            const float* __restrict__ b_ih,
                            const float* __restrict__ W_hh)
{
    int tid = blockIdx.x * blockDim.x + threadIdx.x;
    int nth = gridDim.x * blockDim.x;
    for (int i = tid; i < NROWS * HD; i += nth) g_h[i] = enc[i];

    // Pre-split + reorder W_hh: chunk-major rows, pair-permuted cols.
    // src row = gate*256 + unit; chunk = unit>>5; lr = gate*32 + (unit&31)
    // col k -> (k&~7) | (2*(k&3) + ((k>>2)&1))
    for (int i = tid; i < H3 * HD; i += nth) {
        int row  = i >> 8;
        int k    = i & 255;
        int gate = row >> 8;
        int unit = row & 255;
        int ch   = unit >> 5;
        int lr   = (gate << 5) | (unit & 31);
        int dcol = (k & ~7) | (2 * (k & 3) + ((k >> 2) & 1));
        int dst  = ((ch * WROWS) + lr) * HD + dcol;
        uint32_t hi, lo;
        split_tf32(W_hh[i], hi, lo);
        g_Wp_hi[dst] = hi;
        g_Wp_lo[dst] = lo;
    }

    int warp = tid >> 5, lane = tid & 31, nwarps = nth >> 5;
    for (int j = warp; j < H3; j += nwarps) {
        float sa = 0.0f, sb = 0.0f;
        for (int k = lane; k < HD; k += 32) {
            float w = W_ih[j * HD + k];
            sa += w * w_proj[k];
            sb += w * b_proj[k];
        }
        #pragma unroll
        for (int o = 16; o > 0; o >>= 1) {
            sa += __shfl_xor_sync(0xffffffffu, sa, o);
            sb += __shfl_xor_sync(0xffffffffu, sb, o);
        }
        if (lane == 0) { g_A[j] = sa; g_C[j] = sb + b_ih[j]; }
    }
}

// ---------------------------------------------------------------------------
__device__ __forceinline__ void mma8(float* c, const uint32_t* a,
                                     uint32_t b0, uint32_t b1)
{
    asm volatile(
        "mma.sync.aligned.m16n8k8.row.col.f32.tf32.tf32.f32 "
        "{%0,%1,%2,%3}, {%4,%5,%6,%7}, {%8,%9}, {%0,%1,%2,%3};\n"
        : "+f"(c[0]), "+f"(c[1]), "+f"(c[2]), "+f"(c[3])
        : "r"(a[0]), "r"(a[1]), "r"(a[2]), "r"(a[3]), "r"(b0), "r"(b1));
}

__device__ __forceinline__ void cp16(uint32_t dst_smem, const void* src)
{
    asm volatile("cp.async.cg.shared.global [%0], [%1], 16;\n"
                 :: "r"(dst_smem), "l"(src));
}

__device__ __forceinline__ float fast_sig(float x)
{
    float e, r;
    asm("ex2.approx.ftz.f32 %0, %1;" : "=f"(e) : "f"(-1.4426950408889634f * x));
    asm("rcp.approx.ftz.f32 %0, %1;" : "=f"(r) : "f"(1.0f + e));
    return r;
}
__device__ __forceinline__ float fast_tanh(float x)
{
    float e, r;
    asm("ex2.approx.ftz.f32 %0, %1;" : "=f"(e) : "f"(-2.8853900817779268f * x));
    asm("rcp.approx.ftz.f32 %0, %1;" : "=f"(r) : "f"(1.0f + e));
    return fmaf(2.0f, r, -1.0f);
}

// ---------------------------------------------------------------------------
// Fused decoder: all 24 autoregressive GRU steps in one kernel.
// 16 warps = 4 row-groups x 4 N-groups. Warp = M32 x N24 (r,z,n of 8 units):
// B fragments reused across both m16 row-tiles. Gates warp-local; pred
// reduced across the 4 N-group warps via smem once per step.
// Precision: a_tf32 * (b_hi + b_lo), 2 MMAs per k-octet per tile.
// ---------------------------------------------------------------------------
extern "C" __global__ void __launch_bounds__(NTHREADS, 1)
decode_kernel(const float* __restrict__ b_hh,   // [768]
              const float* __restrict__ w_out,  // [256]
              const float* __restrict__ b_out,  // [1]
              float* __restrict__ out)          // [N,24]
{
    extern __shared__ float smem[];
    float*    sh    = smem;                      // [128][260] h_old
    uint32_t* swb   = (uint32_t*)smem + SWB_W;   // 2 x [hi 96x40 | lo 96x40]
    float*    sA    = smem + SA_W;               // [768]
    float*    sC    = sA + H3;                   // [768]
    float*    sbh   = sC + H3;                   // [768]
    float*    swo   = sbh + H3;                  // [256]
    float*    sx    = smem + SX_W;               // [128] per-row step input
    float*    spred = smem + SPRED_W;            // [128][4] pred partials

    const int tid  = threadIdx.x;
    const int lane = tid & 31;
    const int wid  = tid >> 5;
    const int g    = lane >> 2;          // groupID 0..7
    const int tg   = lane & 3;           // thread-in-group 0..3
    const int rg   = wid >> 2;           // row-group 0..3
    const int ng   = wid & 3;            // N-group 0..3
    const int wr   = rg * 32;            // warp row base (32 rows)
    const int row0 = blockIdx.x * MTILE;

    const uint32_t smem_base = (uint32_t)__cvta_generic_to_shared(smem);
    const uint32_t swb_bytes = smem_base + SWB_W * 4;

    for (int i = tid; i < H3; i += NTHREADS) { sA[i] = g_A[i]; sC[i] = g_C[i]; sbh[i] = b_hh[i]; }
    for (int i = tid; i < HD; i += NTHREADS) swo[i] = w_out[i];
    if (tid < MTILE) sx[tid] = 0.0f;     // x0 = 0 (visible by first gate: s=0 sync)
    const float bo = b_out[0];

    // --- prefetch one W segment: 1536 cp16 slots (768 hi + 768 lo) ---
    // NOTE: 768 is not a power of two; use explicit subtract, NOT a mask.
    auto prefetch_seg = [&](int s) {
        const int ch  = s >> 3, q = s & 7, buf = s & 1;
        const uint32_t dbase = swb_bytes + (uint32_t)(buf * WBUFW) * 4;
        #pragma unroll
        for (int i = 0; i < 3; i++) {
            int e    = i * NTHREADS + tid;       // 0..1535
            int slot = (e < 768) ? e : e - 768;
            int lr = slot >> 3, c4 = slot & 7;
            int gsrc = ((ch * WROWS) + lr) * HD + q * 32 + c4 * 4;
            uint32_t dst = dbase + (uint32_t)(lr * WP + c4 * 4) * 4;
            if (e < 768) cp16(dst,             g_Wp_hi + gsrc);
            else         cp16(dst + WSEGW * 4, g_Wp_lo + gsrc);
        }
        asm volatile("cp.async.commit_group;\n");
    };

    prefetch_seg(0);                     // prime the pipeline

    for (int t = 0; t < TSTEPS; t++) {
        // Stage h_old tile from global (L2-resident); overlaps seg prefetch
        {
            const float4* gh4 = (const float4*)(g_h + (size_t)row0 * HD);
            #pragma unroll 4
            for (int idx = tid; idx < MTILE * (HD / 4); idx += NTHREADS) {
                int r = idx >> 6, c4 = idx & 63;
                float4 v = gh4[idx];
                float* d = sh + r * PITCH + c4 * 4;
                d[0] = v.x; d[1] = v.y; d[2] = v.z; d[3] = v.w;
            }
        }

        float pr[4] = {0.0f, 0.0f, 0.0f, 0.0f};   // pred partials [rt*2+rh]
        float acc[3][2][4];                       // [gate j][rowtile][frag]

        for (int s = 0; s < NSEG; s++) {
            const int ch = s >> 3, q = s & 7, buf = s & 1;

            prefetch_seg((s + 1) & (NSEG - 1));   // wraps into next step

            asm volatile("cp.async.wait_group 1;\n");
            __syncthreads();             // seg data + (s==0) h tile/sx visible

            if (q == 0) {
                #pragma unroll
                for (int j = 0; j < 3; j++)
                    #pragma unroll
                    for (int rt = 0; rt < 2; rt++)
                        #pragma unroll
                        for (int c = 0; c < 4; c++) acc[j][rt][c] = 0.0f;
            }

            const uint32_t* hiP = swb + buf * WBUFW;
            const uint32_t* loP = hiP + WSEGW;

            #pragma unroll
            for (int ks = 0; ks < 4; ks++) {
                const int k0 = q * 32 + ks * 8;
                // A fragments for both row-tiles (rows wr+16rt+{g,g+8})
                uint32_t ua0[4], ua1[4];
                ua0[0] = cvt_tf32(sh[(wr + g)      * PITCH + k0 + tg]);
                ua0[1] = cvt_tf32(sh[(wr + g + 8)  * PITCH + k0 + tg]);
                ua0[2] = cvt_tf32(sh[(wr + g)      * PITCH + k0 + tg + 4]);
                ua0[3] = cvt_tf32(sh[(wr + g + 8)  * PITCH + k0 + tg + 4]);
                ua1[0] = cvt_tf32(sh[(wr + g + 16) * PITCH + k0 + tg]);
                ua1[1] = cvt_tf32(sh[(wr + g + 24) * PITCH + k0 + tg]);
                ua1[2] = cvt_tf32(sh[(wr + g + 16) * PITCH + k0 + tg + 4]);
                ua1[3] = cvt_tf32(sh[(wr + g + 24) * PITCH + k0 + tg + 4]);

                #pragma unroll
                for (int j = 0; j < 3; j++) {
                    const int wb = (32 * j + 8 * ng + g) * WP + ks * 8 + 2 * tg;
                    uint2 bh = *(const uint2*)(hiP + wb);
                    uint2 bl = *(const uint2*)(loP + wb);
                    mma8(acc[j][0], ua0, bh.x, bh.y);   // a * b_hi
                    mma8(acc[j][1], ua1, bh.x, bh.y);
                    mma8(acc[j][0], ua0, bl.x, bl.y);   // a * b_lo
                    mma8(acc[j][1], ua1, bl.x, bl.y);
                }
            }

            if (q == 7) {
                // Gate phase: thread owns unit pair u=ch*32+8ng+2tg (+1)
                // x rows {wr + 16rt + 8rh + g}
                const int u = ch * UC + 8 * ng + 2 * tg;
                const float Ar0 = sA[u],       Ar1 = sA[u + 1];
                const float Az0 = sA[256 + u], Az1 = sA[257 + u];
                const float An0 = sA[512 + u], An1 = sA[513 + u];
                const float Cr0 = sC[u]       + sbh[u],       Cr1 = sC[u + 1]   + sbh[u + 1];
                const float Cz0 = sC[256 + u] + sbh[256 + u], Cz1 = sC[257 + u] + sbh[257 + u];
                const float Cn0 = sC[512 + u], Cn1 = sC[513 + u];
                const float bn0 = sbh[512 + u], bn1 = sbh[513 + u];
                const float wo0 = swo[u], wo1 = swo[u + 1];
                #pragma unroll
                for (int rt = 0; rt < 2; rt++) {
                    #pragma unroll
                    for (int rh = 0; rh < 2; rh++) {
                        const int R = wr + 16 * rt + 8 * rh + g;
                        const float x = sx[R];
                        const int c = 2 * rh;

                        float gr0 = fmaf(x, Ar0, Cr0) + acc[0][rt][c];
                        float gz0 = fmaf(x, Az0, Cz0) + acc[1][rt][c];
                        float r0  = fast_sig(gr0);
                        float z0  = fast_sig(gz0);
                        float n0  = fast_tanh(fmaf(r0, acc[2][rt][c] + bn0, fmaf(x, An0, Cn0)));
                        float ho0 = sh[R * PITCH + u];
                        float hn0 = fmaf(z0, ho0 - n0, n0);

                        float gr1 = fmaf(x, Ar1, Cr1) + acc[0][rt][c + 1];
                        float gz1 = fmaf(x, Az1, Cz1) + acc[1][rt][c + 1];
                        float r1  = fast_sig(gr1);
                        float z1  = fast_sig(gz1);
                        float n1  = fast_tanh(fmaf(r1, acc[2][rt][c + 1] + bn1, fmaf(x, An1, Cn1)));
                        float ho1 = sh[R * PITCH + u + 1];
                        float hn1 = fmaf(z1, ho1 - n1, n1);

                        float2 st; st.x = hn0; st.y = hn1;
                        *(float2*)(g_h + (size_t)(row0 + R) * HD + u) = st;

                        pr[rt * 2 + rh] += fmaf(hn0, wo0, hn1 * wo1);
                    }
                }
            }

            __syncthreads();   // protect buf[cur] before next iter's prefetch
        }

        // pred: reduce over quad lanes (units within warp), then across the
        // 4 N-group warps via smem.
        #pragma unroll
        for (int c = 0; c < 4; c++) {
            pr[c] += __shfl_xor_sync(0xffffffffu, pr[c], 1);
            pr[c] += __shfl_xor_sync(0xffffffffu, pr[c], 2);
        }
        if (tg == 0) {
            #pragma unroll
            for (int rt = 0; rt < 2; rt++)
                #pragma unroll
                for (int rh = 0; rh < 2; rh++) {
                    const int R = wr + 16 * rt + 8 * rh + g;
                    spred[R * 4 + ng] = pr[rt * 2 + rh];
                }
        }
        __syncthreads();
        if (tid < MTILE) {
            float p = spred[tid * 4] + spred[tid * 4 + 1]
                    + spred[tid * 4 + 2] + spred[tid * 4 + 3] + bo;
            out[(size_t)(row0 + tid) * TSTEPS + t] = p;
            sx[tid] = p;      // visible to all by next step's s=0 sync
        }
    }
}

// ---------------------------------------------------------------------------
extern "C" void kernel_launch(void* const* d_in, const int* in_sizes, int n_in,
                              void* d_out, int out_size)
{
    const float* enc    = (const float*)d_in[0];
    const float* w_proj = (const float*)d_in[1];
    const float* b_proj = (const float*)d_in[2];
    const float* W_ih   = (const float*)d_in[3];
    const float* b_ih   = (const float*)d_in[4];
    const float* W_hh   = (const float*)d_in[5];
    const float* b_hh   = (const float*)d_in[6];
    const float* w_out  = (const float*)d_in[7];
    const float* b_out  = (const float*)d_in[8];
    float* out = (float*)d_out;

    cudaFuncSetAttribute(decode_kernel,
                         cudaFuncAttributeMaxDynamicSharedMemorySize, SMEM_BYTES);

    init_kernel<<<256, 256>>>(enc, w_proj, b_proj, W_ih, b_ih, W_hh);
    decode_kernel<<<NBLK, NTHREADS, SMEM_BYTES>>>(b_hh, w_out, b_out, out);
}

// round 17
// speedup vs baseline: 1.1330x; 1.1330x over previous
#include <cuda_runtime.h>
#include <math.h>
#include <stdint.h>

// Problem constants
#define NROWS   16384
#define HD      256
#define H3      768
#define TSTEPS  24

// Tiling
#define MTILE   128                  // rows per CTA
#define NBLK    (NROWS / MTILE)      // 128 CTAs
#define NTHREADS 256                 // 8 warps: 2 row-groups x 4 N-groups
#define UC      32                   // hidden units per chunk
#define NCH     (HD / UC)            // 8 chunks
#define NSEG    64                   // 8 chunks x 8 K-segments of 32
#define PITCH   260                  // h smem pitch (stride%32==4, conflict-free)
#define WP      40                   // W segment row pitch
#define WROWS   96                   // 3 gates x 32 units
#define WSEGW   (WROWS * WP)         // 3840 words per (hi|lo) segment
#define WBUFW   (2 * WSEGW)          // 7680 words per buffer (hi+lo)

// Persistent device state
__device__ float    g_h[NROWS * HD];        // hidden state [N,H] fp32
__device__ float    g_A[H3];                // W_ih @ w_proj
__device__ float    g_C[H3];                // W_ih @ b_proj + b_ih
// W_hh pre-split tf32 hi/lo, chunk-major [8][96][256], cols pair-permuted
__device__ uint32_t g_Wp_hi[NCH * WROWS * HD];
__device__ uint32_t g_Wp_lo[NCH * WROWS * HD];

// smem words
#define SH_W    (MTILE * PITCH)              // 33280 (tf32 bits of h)
#define SWB_W   SH_W                         // W buffers start
#define SA_W    (SWB_W + 2 * WBUFW)          // 48640
#define SX_W    (SA_W + 3 * H3 + HD)         // 51200
#define SPRED_W (SX_W + MTILE)               // 51328
#define SMEM_WORDS (SPRED_W + MTILE * 4)     // 51840
#define SMEM_BYTES (SMEM_WORDS * 4)          // 207360

// ---------------------------------------------------------------------------
__device__ __forceinline__ void split_tf32(float v, uint32_t& hi, uint32_t& lo)
{
    uint32_t h;
    asm("cvt.rna.tf32.f32 %0, %1;" : "=r"(h) : "f"(v));
    float lf = v - __uint_as_float(h);
    uint32_t l;
    asm("cvt.rna.tf32.f32 %0, %1;" : "=r"(l) : "f"(lf));
    hi = h; lo = l;
}

__device__ __forceinline__ uint32_t cvt_tf32(float v)
{
    uint32_t h;
    asm("cvt.rna.tf32.f32 %0, %1;" : "=r"(h) : "f"(v));
    return h;
}

__global__ void init_kernel(const float* __restrict__ enc,
                            const float* __restrict__ w_proj,
                            const float* __restrict__ b_proj,
                            const float* __restrict__ W_ih,
                            const float* __restrict__ b_ih,
                            const float* __restrict__ W_hh)
{
    int tid = blockIdx.x * blockDim.x + threadIdx.x;
    int nth = gridDim.x * blockDim.x;
    for (int i = tid; i < NROWS * HD; i += nth) g_h[i] = enc[i];

    // Pre-split + reorder W_hh: chunk-major rows, pair-permuted cols.
    // src row = gate*256 + unit; chunk = unit>>5; lr = gate*32 + (unit&31)
    // col k -> (k&~7) | (2*(k&3) + ((k>>2)&1))
    for (int i = tid; i < H3 * HD; i += nth) {
        int row  = i >> 8;
        int k    = i & 255;
        int gate = row >> 8;
        int unit = row & 255;
        int ch   = unit >> 5;
        int lr   = (gate << 5) | (unit & 31);
        int dcol = (k & ~7) | (2 * (k & 3) + ((k >> 2) & 1));
        int dst  = ((ch * WROWS) + lr) * HD + dcol;
        uint32_t hi, lo;
        split_tf32(W_hh[i], hi, lo);
        g_Wp_hi[dst] = hi;
        g_Wp_lo[dst] = lo;
    }

    int warp = tid >> 5, lane = tid & 31, nwarps = nth >> 5;
    for (int j = warp; j < H3; j += nwarps) {
        float sa = 0.0f, sb = 0.0f;
        for (int k = lane; k < HD; k += 32) {
            float w = W_ih[j * HD + k];
            sa += w * w_proj[k];
            sb += w * b_proj[k];
        }
        #pragma unroll
        for (int o = 16; o > 0; o >>= 1) {
            sa += __shfl_xor_sync(0xffffffffu, sa, o);
            sb += __shfl_xor_sync(0xffffffffu, sb, o);
        }
        if (lane == 0) { g_A[j] = sa; g_C[j] = sb + b_ih[j]; }
    }
}

// ---------------------------------------------------------------------------
__device__ __forceinline__ void mma8(float* c, const uint32_t* a,
                                     uint32_t b0, uint32_t b1)
{
    asm volatile(
        "mma.sync.aligned.m16n8k8.row.col.f32.tf32.tf32.f32 "
        "{%0,%1,%2,%3}, {%4,%5,%6,%7}, {%8,%9}, {%0,%1,%2,%3};\n"
        : "+f"(c[0]), "+f"(c[1]), "+f"(c[2]), "+f"(c[3])
        : "r"(a[0]), "r"(a[1]), "r"(a[2]), "r"(a[3]), "r"(b0), "r"(b1));
}

__device__ __forceinline__ void cp16(uint32_t dst_smem, const void* src)
{
    asm volatile("cp.async.cg.shared.global [%0], [%1], 16;\n"
                 :: "r"(dst_smem), "l"(src));
}

__device__ __forceinline__ float fast_sig(float x)
{
    float e, r;
    asm("ex2.approx.ftz.f32 %0, %1;" : "=f"(e) : "f"(-1.4426950408889634f * x));
    asm("rcp.approx.ftz.f32 %0, %1;" : "=f"(r) : "f"(1.0f + e));
    return r;
}
__device__ __forceinline__ float fast_tanh(float x)
{
    float e, r;
    asm("ex2.approx.ftz.f32 %0, %1;" : "=f"(e) : "f"(-2.8853900817779268f * x));
    asm("rcp.approx.ftz.f32 %0, %1;" : "=f"(r) : "f"(1.0f + e));
    return fmaf(2.0f, r, -1.0f);
}

// ---------------------------------------------------------------------------
// Fused decoder: all 24 autoregressive GRU steps in one kernel.
// 8 warps = 2 row-groups x 4 N-groups. Warp = M64 x N24 (r,z,n of 8 units):
// B fragments loaded once per octet, reused across 4 m16 row-tiles.
// h staged into smem as PRE-CONVERTED tf32 bits (cvt once per value per
// step); mainloop A loads are raw LDS. Gates read h_old from the same tf32
// bits (tf32 == fp32 with truncated mantissa; adds ~2^-11 rel on z*h term,
// same magnitude as existing A rounding).
// Precision: a_tf32 * (b_hi + b_lo), 2 MMAs per k-octet per n8-tile.
// ---------------------------------------------------------------------------
extern "C" __global__ void __launch_bounds__(NTHREADS, 1)
decode_kernel(const float* __restrict__ b_hh,   // [768]
              const float* __restrict__ w_out,  // [256]
              const float* __restrict__ b_out,  // [1]
              float* __restrict__ out)          // [N,24]
{
    extern __shared__ float smem[];
    uint32_t* sh    = (uint32_t*)smem;           // [128][260] h_old (tf32 bits)
    uint32_t* swb   = (uint32_t*)smem + SWB_W;   // 2 x [hi 96x40 | lo 96x40]
    float*    sA    = smem + SA_W;               // [768]
    float*    sC    = sA + H3;                   // [768]
    float*    sbh   = sC + H3;                   // [768]
    float*    swo   = sbh + H3;                  // [256]
    float*    sx    = smem + SX_W;               // [128] per-row step input
    float*    spred = smem + SPRED_W;            // [128][4] pred partials

    const int tid  = threadIdx.x;
    const int lane = tid & 31;
    const int wid  = tid >> 5;
    const int g    = lane >> 2;          // groupID 0..7
    const int tg   = lane & 3;           // thread-in-group 0..3
    const int rg   = wid >> 2;           // row-group 0..1
    const int ng   = wid & 3;            // N-group 0..3
    const int wr   = rg * 64;            // warp row base (64 rows)
    const int row0 = blockIdx.x * MTILE;

    const uint32_t smem_base = (uint32_t)__cvta_generic_to_shared(smem);
    const uint32_t swb_bytes = smem_base + SWB_W * 4;

    for (int i = tid; i < H3; i += NTHREADS) { sA[i] = g_A[i]; sC[i] = g_C[i]; sbh[i] = b_hh[i]; }
    for (int i = tid; i < HD; i += NTHREADS) swo[i] = w_out[i];
    if (tid < MTILE) sx[tid] = 0.0f;     // x0 = 0 (visible by first gate: s=0 sync)
    const float bo = b_out[0];

    // --- prefetch one W segment (3 x (hi,lo) cp16 per thread + commit) ---
    auto prefetch_seg = [&](int s) {
        const int ch  = s >> 3, q = s & 7, buf = s & 1;
        const uint32_t dbase = swb_bytes + (uint32_t)(buf * WBUFW) * 4;
        #pragma unroll
        for (int i = 0; i < 3; i++) {
            int e  = i * NTHREADS + tid;     // 0..767
            int lr = e >> 3, c4 = e & 7;
            int gsrc = ((ch * WROWS) + lr) * HD + q * 32 + c4 * 4;
            uint32_t dst = dbase + (uint32_t)(lr * WP + c4 * 4) * 4;
            cp16(dst,             g_Wp_hi + gsrc);
            cp16(dst + WSEGW * 4, g_Wp_lo + gsrc);
        }
        asm volatile("cp.async.commit_group;\n");
    };

    prefetch_seg(0);                     // prime the pipeline

    for (int t = 0; t < TSTEPS; t++) {
        // Stage h_old tile: fp32 from global, convert to tf32 bits, store.
        {
            const float4* gh4 = (const float4*)(g_h + (size_t)row0 * HD);
            #pragma unroll 4
            for (int idx = tid; idx < MTILE * (HD / 4); idx += NTHREADS) {
                int r = idx >> 6, c4 = idx & 63;
                float4 v = gh4[idx];
                uint4 u;
                u.x = cvt_tf32(v.x); u.y = cvt_tf32(v.y);
                u.z = cvt_tf32(v.z); u.w = cvt_tf32(v.w);
                *(uint4*)(sh + r * PITCH + c4 * 4) = u;
            }
        }

        float pr[8];                              // pred partials [rt*2+rh]
        #pragma unroll
        for (int i = 0; i < 8; i++) pr[i] = 0.0f;
        float acc[3][4][4];                       // [gate j][rowtile][frag]

        for (int s = 0; s < NSEG; s++) {
            const int ch = s >> 3, q = s & 7, buf = s & 1;

            prefetch_seg((s + 1) & (NSEG - 1));   // wraps into next step

            asm volatile("cp.async.wait_group 1;\n");
            __syncthreads();             // seg data + (s==0) h tile/sx visible

            if (q == 0) {
                #pragma unroll
                for (int j = 0; j < 3; j++)
                    #pragma unroll
                    for (int rt = 0; rt < 4; rt++)
                        #pragma unroll
                        for (int c = 0; c < 4; c++) acc[j][rt][c] = 0.0f;
            }

            const uint32_t* hiP = swb + buf * WBUFW;
            const uint32_t* loP = hiP + WSEGW;

            #pragma unroll
            for (int ks = 0; ks < 4; ks++) {
                const int k0 = q * 32 + ks * 8;

                // B fragments once per octet (reused by all 4 row-tiles)
                uint2 bh[3], bl[3];
                #pragma unroll
                for (int j = 0; j < 3; j++) {
                    const int wb = (32 * j + 8 * ng + g) * WP + ks * 8 + 2 * tg;
                    bh[j] = *(const uint2*)(hiP + wb);
                    bl[j] = *(const uint2*)(loP + wb);
                }

                #pragma unroll
                for (int rt = 0; rt < 4; rt++) {
                    const int r0r = (wr + 16 * rt + g) * PITCH + k0;
                    const int r1r = (wr + 16 * rt + g + 8) * PITCH + k0;
                    uint32_t ua[4];
                    ua[0] = sh[r0r + tg];
                    ua[1] = sh[r1r + tg];
                    ua[2] = sh[r0r + tg + 4];
                    ua[3] = sh[r1r + tg + 4];
                    #pragma unroll
                    for (int j = 0; j < 3; j++) {
                        mma8(acc[j][rt], ua, bh[j].x, bh[j].y);  // a * b_hi
                        mma8(acc[j][rt], ua, bl[j].x, bl[j].y);  // a * b_lo
                    }
                }
            }

            if (q == 7) {
                // Gate phase: thread owns unit pair u=ch*32+8ng+2tg (+1)
                // x rows {wr + 16rt + 8rh + g}, rt 0..3
                const int u = ch * UC + 8 * ng + 2 * tg;
                const float Ar0 = sA[u],       Ar1 = sA[u + 1];
                const float Az0 = sA[256 + u], Az1 = sA[257 + u];
                const float An0 = sA[512 + u], An1 = sA[513 + u];
                const float Cr0 = sC[u]       + sbh[u],       Cr1 = sC[u + 1]   + sbh[u + 1];
                const float Cz0 = sC[256 + u] + sbh[256 + u], Cz1 = sC[257 + u] + sbh[257 + u];
                const float Cn0 = sC[512 + u], Cn1 = sC[513 + u];
                const float bn0 = sbh[512 + u], bn1 = sbh[513 + u];
                const float wo0 = swo[u], wo1 = swo[u + 1];
                #pragma unroll
                for (int rt = 0; rt < 4; rt++) {
                    #pragma unroll
                    for (int rh = 0; rh < 2; rh++) {
                        const int R = wr + 16 * rt + 8 * rh + g;
                        const float x = sx[R];
                        const int c = 2 * rh;

                        // h_old from tf32 bits (valid fp32 bit patterns)
                        uint2 ho = *(const uint2*)(sh + R * PITCH + u);
                        float ho0 = __uint_as_float(ho.x);
                        float ho1 = __uint_as_float(ho.y);

                        float gr0 = fmaf(x, Ar0, Cr0) + acc[0][rt][c];
                        float gz0 = fmaf(x, Az0, Cz0) + acc[1][rt][c];
                        float r0  = fast_sig(gr0);
                        float z0  = fast_sig(gz0);
                        float n0  = fast_tanh(fmaf(r0, acc[2][rt][c] + bn0, fmaf(x, An0, Cn0)));
                        float hn0 = fmaf(z0, ho0 - n0, n0);

                        float gr1 = fmaf(x, Ar1, Cr1) + acc[0][rt][c + 1];
                        float gz1 = fmaf(x, Az1, Cz1) + acc[1][rt][c + 1];
                        float r1  = fast_sig(gr1);
                        float z1  = fast_sig(gz1);
                        float n1  = fast_tanh(fmaf(r1, acc[2][rt][c + 1] + bn1, fmaf(x, An1, Cn1)));
                        float hn1 = fmaf(z1, ho1 - n1, n1);

                        float2 st; st.x = hn0; st.y = hn1;
                        *(float2*)(g_h + (size_t)(row0 + R) * HD + u) = st;

                        pr[rt * 2 + rh] += fmaf(hn0, wo0, hn1 * wo1);
                    }
                }
            }

            __syncthreads();   // protect buf[cur] before next iter's prefetch
        }

        // pred: reduce over quad lanes (units within warp), then across the
        // 4 N-group warps via smem.
        #pragma unroll
        for (int c = 0; c < 8; c++) {
            pr[c] += __shfl_xor_sync(0xffffffffu, pr[c], 1);
            pr[c] += __shfl_xor_sync(0xffffffffu, pr[c], 2);
        }
        if (tg == 0) {
            #pragma unroll
            for (int rt = 0; rt < 4; rt++)
                #pragma unroll
                for (int rh = 0; rh < 2; rh++) {
                    const int R = wr + 16 * rt + 8 * rh + g;
                    spred[R * 4 + ng] = pr[rt * 2 + rh];
                }
        }
        __syncthreads();
        if (tid < MTILE) {
            float p = spred[tid * 4] + spred[tid * 4 + 1]
                    + spred[tid * 4 + 2] + spred[tid * 4 + 3] + bo;
            out[(size_t)(row0 + tid) * TSTEPS + t] = p;
            sx[tid] = p;      // visible to all by next step's s=0 sync
        }
    }
}

// ---------------------------------------------------------------------------
extern "C" void kernel_launch(void* const* d_in, const int* in_sizes, int n_in,
                              void* d_out, int out_size)
{
    const float* enc    = (const float*)d_in[0];
    const float* w_proj = (const float*)d_in[1];
    const float* b_proj = (const float*)d_in[2];
    const float* W_ih   = (const float*)d_in[3];
    const float* b_ih   = (const float*)d_in[4];
    const float* W_hh   = (const float*)d_in[5];
    const float* b_hh   = (const float*)d_in[6];
    const float* w_out  = (const float*)d_in[7];
    const float* b_out  = (const float*)d_in[8];
    float* out = (float*)d_out;

    cudaFuncSetAttribute(decode_kernel,
                         cudaFuncAttributeMaxDynamicSharedMemorySize, SMEM_BYTES);

    init_kernel<<<256, 256>>>(enc, w_proj, b_proj, W_ih, b_ih, W_hh);
    decode_kernel<<<NBLK, NTHREADS, SMEM_BYTES>>>(b_hh, w_out, b_out, out);
}